// round 5
// baseline (speedup 1.0000x reference)
#include <cuda_runtime.h>
#include <cuda_fp16.h>
#include <cstdint>

// Problem constants (from reference)
#define B_      2
#define N_IN    163842
#define N_OUT   40962
#define C_      128
#define K_      7
#define INV_2SIG2 3.125f   // 1/(2*0.4^2)

#define DOWN_ELEMS (B_ * N_OUT * C_)   // 10,486,272 floats (~42 MB)

// Scratch (allocation-free rule: __device__ globals).
// Zero-initialized at module load; convert_kernel restores the zero invariant
// after consuming, so no separate zero pass is needed.
__device__ float  g_down[DOWN_ELEMS];
__device__ float  g_denom[N_OUT];
// fp16 normalized intermediate, batch-interleaved: row j = [b0 c0..127][b1 c0..127]
// = 256 halves = 512 contiguous bytes per candidate row.
__device__ __half g_half[(size_t)N_OUT * 256];

// Bit-cast helper (no SASS cost)
__device__ __forceinline__ unsigned h2_to_u(__half2 h) {
    unsigned u; *reinterpret_cast<__half2*>(&u) = h; return u;
}
__device__ __forceinline__ __half2 u_to_h2(unsigned u) {
    return *reinterpret_cast<__half2*>(&u);
}

// ---------------------------------------------------------------------------
// Kernel 1: scatter-add  down[b, parent[n], :] += omega[n] * x[b, n, :]
//           denom[parent[n]] += omega[n]
// TWO n per warp; 4 independent streaming (ldcs) LDG.128 front-batched
// (MLP=4) before the REDs. ldcs keeps the hot g_down RMW set resident in L2.
// ---------------------------------------------------------------------------
__device__ __forceinline__ void red_add_v4(float* addr, float4 v) {
    asm volatile("red.global.add.v4.f32 [%0], {%1, %2, %3, %4};"
                 :: "l"(addr), "f"(v.x), "f"(v.y), "f"(v.z), "f"(v.w)
                 : "memory");
}
__device__ __forceinline__ float4 ldcs_v4(const float4* p) {
    float4 v;
    asm volatile("ld.global.cs.v4.f32 {%0,%1,%2,%3}, [%4];"
                 : "=f"(v.x), "=f"(v.y), "=f"(v.z), "=f"(v.w) : "l"(p));
    return v;
}

__global__ void __launch_bounds__(256)
scatter_kernel(const float* __restrict__ x,
               const float* __restrict__ omega,
               const int*   __restrict__ parent)
{
    int w    = (blockIdx.x * blockDim.x + threadIdx.x) >> 5;
    int lane = threadIdx.x & 31;
    const int n0 = 2 * w;
    const int n1 = n0 + 1;
    if (n0 >= N_IN) return;   // N_IN even -> n1 also valid

    const int   p0  = __ldg(parent + n0);
    const int   p1  = __ldg(parent + n1);
    const float om0 = __ldg(omega + n0);
    const float om1 = __ldg(omega + n1);

    // 4 independent streaming loads (front-batched)
    const float4 a0 = ldcs_v4(reinterpret_cast<const float4*>(x + (size_t)n0 * C_) + lane);
    const float4 a1 = ldcs_v4(reinterpret_cast<const float4*>(x + (size_t)(N_IN + n0) * C_) + lane);
    const float4 b0 = ldcs_v4(reinterpret_cast<const float4*>(x + (size_t)n1 * C_) + lane);
    const float4 b1 = ldcs_v4(reinterpret_cast<const float4*>(x + (size_t)(N_IN + n1) * C_) + lane);

    red_add_v4(g_down + (size_t)p0 * C_ + lane * 4,
               make_float4(a0.x * om0, a0.y * om0, a0.z * om0, a0.w * om0));
    red_add_v4(g_down + (size_t)(N_OUT + p0) * C_ + lane * 4,
               make_float4(a1.x * om0, a1.y * om0, a1.z * om0, a1.w * om0));
    red_add_v4(g_down + (size_t)p1 * C_ + lane * 4,
               make_float4(b0.x * om1, b0.y * om1, b0.z * om1, b0.w * om1));
    red_add_v4(g_down + (size_t)(N_OUT + p1) * C_ + lane * 4,
               make_float4(b1.x * om1, b1.y * om1, b1.z * om1, b1.w * om1));

    if (lane == 0) {
        atomicAdd(g_denom + p0, om0);
        atomicAdd(g_denom + p1, om1);
    }
}

// ---------------------------------------------------------------------------
// Kernel 2: convert  g_half[j] = fp16( g_down[:, j, :] / clip(denom[j]) )
// Then re-zero g_down rows and denom[j] (restores entry invariant).
// One warp per j.
// ---------------------------------------------------------------------------
__global__ void __launch_bounds__(256)
convert_kernel()
{
    int w    = (blockIdx.x * blockDim.x + threadIdx.x) >> 5;
    int lane = threadIdx.x & 31;
    if (w >= N_OUT) return;
    const int j = w;

    const float inv = 1.f / fmaxf(g_denom[j], 1e-8f);

    float4* p0 = reinterpret_cast<float4*>(g_down + (size_t)j * C_) + lane;
    float4* p1 = reinterpret_cast<float4*>(g_down + (size_t)(N_OUT + j) * C_) + lane;
    const float4 v0 = *p0;
    const float4 v1 = *p1;

    __half2 h00 = __floats2half2_rn(v0.x * inv, v0.y * inv);
    __half2 h01 = __floats2half2_rn(v0.z * inv, v0.w * inv);
    __half2 h10 = __floats2half2_rn(v1.x * inv, v1.y * inv);
    __half2 h11 = __floats2half2_rn(v1.z * inv, v1.w * inv);

    uint2* row = reinterpret_cast<uint2*>(g_half + (size_t)j * 256);
    row[lane]      = make_uint2(h2_to_u(h00), h2_to_u(h01));
    row[32 + lane] = make_uint2(h2_to_u(h10), h2_to_u(h11));

    // restore zero invariant for the next call
    const float4 z = make_float4(0.f, 0.f, 0.f, 0.f);
    *p0 = z;
    *p1 = z;
    if (lane == 0) g_denom[j] = 0.f;
}

// ---------------------------------------------------------------------------
// Kernel 3: gather  out[b,n,:] = sum_k coef_k * g_half[cand[n,k], b, :]
//   coef_k = w_k / clip(sum_k w_k);  w_k = exp(-delta^2 * INV_2SIG2) * mask
// One warp per n. Each k-step is ONE LDG.128 per lane covering the whole
// 512B row: lanes 0..15 hold batch0 channels lane*8..+7, lanes 16..31 hold
// batch1 channels (lane-16)*8..+7. Output stores: 2 float4 per lane,
// 512B contiguous per (b, warp).
// ---------------------------------------------------------------------------
__global__ void __launch_bounds__(256)
gather_kernel(const float* __restrict__ delta,
              const float* __restrict__ mask,
              const int*   __restrict__ cand,
              float*       __restrict__ out)
{
    int w    = (blockIdx.x * blockDim.x + threadIdx.x) >> 5;
    int lane = threadIdx.x & 31;
    if (w >= N_IN) return;
    const int n = w;

    int   j = 0;
    float e = 0.f;
    if (lane < K_) {
        const int idx = n * K_ + lane;
        j = __ldg(cand + idx);
        const float d = __ldg(delta + idx);
        e = __expf(-d * d * INV_2SIG2) * __ldg(mask + idx);
    }

    // sum of w over lanes 0..6 (others contribute 0); lanes 0..7 closed
    // under xor {1,2,4}
    float s = e;
    s += __shfl_xor_sync(0xffffffffu, s, 1);
    s += __shfl_xor_sync(0xffffffffu, s, 2);
    s += __shfl_xor_sync(0xffffffffu, s, 4);
    s  = __shfl_sync(0xffffffffu, s, 0);

    const float coef = e / fmaxf(s, 1e-8f);

    float2 acc[4] = { {0.f,0.f}, {0.f,0.f}, {0.f,0.f}, {0.f,0.f} };

#pragma unroll
    for (int k = 0; k < K_; k++) {
        const int   jk = __shfl_sync(0xffffffffu, j,    k);
        const float ck = __shfl_sync(0xffffffffu, coef, k);
        // one 16B load per lane; whole row = 512B, perfectly coalesced
        const uint4 h = __ldg(reinterpret_cast<const uint4*>(g_half + (size_t)jk * 256) + lane);

        const float2 f0 = __half22float2(u_to_h2(h.x));
        const float2 f1 = __half22float2(u_to_h2(h.y));
        const float2 f2 = __half22float2(u_to_h2(h.z));
        const float2 f3 = __half22float2(u_to_h2(h.w));

        acc[0].x = fmaf(ck, f0.x, acc[0].x); acc[0].y = fmaf(ck, f0.y, acc[0].y);
        acc[1].x = fmaf(ck, f1.x, acc[1].x); acc[1].y = fmaf(ck, f1.y, acc[1].y);
        acc[2].x = fmaf(ck, f2.x, acc[2].x); acc[2].y = fmaf(ck, f2.y, acc[2].y);
        acc[3].x = fmaf(ck, f3.x, acc[3].x); acc[3].y = fmaf(ck, f3.y, acc[3].y);
    }

    // lanes 0..15 -> batch 0, channels lane*8..+7 ; lanes 16..31 -> batch 1
    const int b   = lane >> 4;
    const int ch0 = (lane & 15) * 8;
    float* dst = out + (size_t)b * N_IN * C_ + (size_t)n * C_ + ch0;
    reinterpret_cast<float4*>(dst)[0] = make_float4(acc[0].x, acc[0].y, acc[1].x, acc[1].y);
    reinterpret_cast<float4*>(dst)[1] = make_float4(acc[2].x, acc[2].y, acc[3].x, acc[3].y);
}

// ---------------------------------------------------------------------------
// Launch
// Inputs (metadata order): 0=x, 1=omega, 2=delta, 3=cand_mask, 4=parent_idx,
//                          5=cand_idx. Output: float32 [B, N_IN, C].
// ---------------------------------------------------------------------------
extern "C" void kernel_launch(void* const* d_in, const int* in_sizes, int n_in,
                              void* d_out, int out_size)
{
    const float* x      = (const float*)d_in[0];
    const float* omega  = (const float*)d_in[1];
    const float* delta  = (const float*)d_in[2];
    const float* mask   = (const float*)d_in[3];
    const int*   parent = (const int*)  d_in[4];
    const int*   cand   = (const int*)  d_in[5];
    float*       out    = (float*)d_out;

    const int blocks_sc  = ((N_IN / 2) * 32 + 255) / 256;  // two n per warp
    const int blocks_in  = (N_IN  * 32 + 255) / 256;       // one warp per n
    const int blocks_out = (N_OUT * 32 + 255) / 256;       // one warp per j

    scatter_kernel<<<blocks_sc, 256>>>(x, omega, parent);
    convert_kernel<<<blocks_out, 256>>>();
    gather_kernel<<<blocks_in, 256>>>(delta, mask, cand, out);
}

// round 6
// speedup vs baseline: 1.1525x; 1.1525x over previous
#include <cuda_runtime.h>
#include <cuda_fp16.h>
#include <cstdint>

// Problem constants (from reference)
#define B_      2
#define N_IN    163842
#define N_OUT   40962
#define C_      128
#define K_      7
#define INV_2SIG2 3.125f   // 1/(2*0.4^2)

#define DOWN_ELEMS (B_ * N_OUT * C_)   // 10,486,272 floats (~42 MB)

// Scratch (allocation-free rule: __device__ globals).
// Zero-initialized at module load; convert_kernel restores the zero invariant
// after consuming, so no separate zero pass is needed.
__device__ float  g_down[DOWN_ELEMS];
__device__ float  g_denom[N_OUT];
// fp16 normalized intermediate, batch-interleaved: row j = [b0 c0..127][b1 c0..127]
// = 256 halves = 512 contiguous bytes per candidate row.
__device__ __half g_half[(size_t)N_OUT * 256];

// Bit-cast helpers (no SASS cost)
__device__ __forceinline__ unsigned h2_to_u(__half2 h) {
    unsigned u; *reinterpret_cast<__half2*>(&u) = h; return u;
}
__device__ __forceinline__ __half2 u_to_h2(unsigned u) {
    return *reinterpret_cast<__half2*>(&u);
}

// ---------------------------------------------------------------------------
// Kernel 1: scatter-add  down[b, parent[n], :] += omega[n] * x[b, n, :]
//           denom[parent[n]] += omega[n]
// One warp per n (R4 layout — best measured). Streaming loads (ldcs) on x:
// verified to cut DRAM traffic 248->216 MB by not evicting the hot g_down
// RMW set from L2.
// ---------------------------------------------------------------------------
__device__ __forceinline__ void red_add_v4(float* addr, float4 v) {
    asm volatile("red.global.add.v4.f32 [%0], {%1, %2, %3, %4};"
                 :: "l"(addr), "f"(v.x), "f"(v.y), "f"(v.z), "f"(v.w)
                 : "memory");
}
__device__ __forceinline__ float4 ldcs_v4(const float4* p) {
    float4 v;
    asm volatile("ld.global.cs.v4.f32 {%0,%1,%2,%3}, [%4];"
                 : "=f"(v.x), "=f"(v.y), "=f"(v.z), "=f"(v.w) : "l"(p));
    return v;
}

__global__ void __launch_bounds__(256)
scatter_kernel(const float* __restrict__ x,
               const float* __restrict__ omega,
               const int*   __restrict__ parent)
{
    int w    = (blockIdx.x * blockDim.x + threadIdx.x) >> 5;
    int lane = threadIdx.x & 31;
    if (w >= N_IN) return;
    const int n = w;

    const int   p  = __ldg(parent + n);   // uniform within warp -> broadcast
    const float om = __ldg(omega + n);

    const float4 v0i = ldcs_v4(reinterpret_cast<const float4*>(x + (size_t)n * C_) + lane);
    const float4 v1i = ldcs_v4(reinterpret_cast<const float4*>(x + (size_t)(N_IN + n) * C_) + lane);

    float4 v0 = make_float4(v0i.x * om, v0i.y * om, v0i.z * om, v0i.w * om);
    float4 v1 = make_float4(v1i.x * om, v1i.y * om, v1i.z * om, v1i.w * om);

    red_add_v4(g_down + (size_t)p * C_ + lane * 4, v0);
    red_add_v4(g_down + (size_t)(N_OUT + p) * C_ + lane * 4, v1);

    if (lane == 0) atomicAdd(g_denom + p, om);
}

// ---------------------------------------------------------------------------
// Kernel 2: convert  g_half[j] = fp16( g_down[:, j, :] / clip(denom[j]) )
// Then re-zero g_down rows and denom[j] (restores entry invariant).
// One warp per j.
// ---------------------------------------------------------------------------
__global__ void __launch_bounds__(256)
convert_kernel()
{
    int w    = (blockIdx.x * blockDim.x + threadIdx.x) >> 5;
    int lane = threadIdx.x & 31;
    if (w >= N_OUT) return;
    const int j = w;

    const float inv = 1.f / fmaxf(g_denom[j], 1e-8f);

    float4* p0 = reinterpret_cast<float4*>(g_down + (size_t)j * C_) + lane;
    float4* p1 = reinterpret_cast<float4*>(g_down + (size_t)(N_OUT + j) * C_) + lane;
    const float4 v0 = *p0;
    const float4 v1 = *p1;

    __half2 h00 = __floats2half2_rn(v0.x * inv, v0.y * inv);
    __half2 h01 = __floats2half2_rn(v0.z * inv, v0.w * inv);
    __half2 h10 = __floats2half2_rn(v1.x * inv, v1.y * inv);
    __half2 h11 = __floats2half2_rn(v1.z * inv, v1.w * inv);

    uint2* row = reinterpret_cast<uint2*>(g_half + (size_t)j * 256);
    row[lane]      = make_uint2(h2_to_u(h00), h2_to_u(h01));
    row[32 + lane] = make_uint2(h2_to_u(h10), h2_to_u(h11));

    // restore zero invariant for the next call
    const float4 z = make_float4(0.f, 0.f, 0.f, 0.f);
    *p0 = z;
    *p1 = z;
    if (lane == 0) g_denom[j] = 0.f;
}

// ---------------------------------------------------------------------------
// Kernel 3: gather  out[b,n,:] = sum_k coef_k * g_half[cand[n,k], b, :]
//   coef_k = w_k / clip(sum_k w_k);  w_k = exp(-delta^2 * INV_2SIG2) * mask
// One warp per n; two independent LDG.64 per k (R4 layout — measured faster
// than one LDG.128: cross-LDG wavefronts cost 1.0 cyc/wf vs 2.07 within-LDG).
// Output written with streaming stores (stcs) to keep g_half hot in L2.
// ---------------------------------------------------------------------------
__device__ __forceinline__ void stcs_v4(float4* p, float4 v) {
    asm volatile("st.global.cs.v4.f32 [%0], {%1,%2,%3,%4};"
                 :: "l"(p), "f"(v.x), "f"(v.y), "f"(v.z), "f"(v.w) : "memory");
}

__global__ void __launch_bounds__(256)
gather_kernel(const float* __restrict__ delta,
              const float* __restrict__ mask,
              const int*   __restrict__ cand,
              float*       __restrict__ out)
{
    int w    = (blockIdx.x * blockDim.x + threadIdx.x) >> 5;
    int lane = threadIdx.x & 31;
    if (w >= N_IN) return;
    const int n = w;

    int   j = 0;
    float e = 0.f;
    if (lane < K_) {
        const int idx = n * K_ + lane;
        j = __ldg(cand + idx);
        const float d = __ldg(delta + idx);
        e = __expf(-d * d * INV_2SIG2) * __ldg(mask + idx);
    }

    // sum of w over lanes 0..6 (lane 7 contributes 0); lanes 0..7 closed
    // under xor {1,2,4}
    float s = e;
    s += __shfl_xor_sync(0xffffffffu, s, 1);
    s += __shfl_xor_sync(0xffffffffu, s, 2);
    s += __shfl_xor_sync(0xffffffffu, s, 4);
    s  = __shfl_sync(0xffffffffu, s, 0);

    const float coef = e / fmaxf(s, 1e-8f);  // lanes >= K_: e=0 -> 0

    float4 acc0 = make_float4(0.f, 0.f, 0.f, 0.f);
    float4 acc1 = make_float4(0.f, 0.f, 0.f, 0.f);

#pragma unroll
    for (int k = 0; k < K_; k++) {
        const int   jk = __shfl_sync(0xffffffffu, j,    k);
        const float ck = __shfl_sync(0xffffffffu, coef, k);
        const uint2* row = reinterpret_cast<const uint2*>(g_half + (size_t)jk * 256);
        const uint2 h0 = __ldg(row + lane);        // b0: channels lane*4..+3
        const uint2 h1 = __ldg(row + 32 + lane);   // b1

        const float2 f00 = __half22float2(u_to_h2(h0.x));
        const float2 f01 = __half22float2(u_to_h2(h0.y));
        const float2 f10 = __half22float2(u_to_h2(h1.x));
        const float2 f11 = __half22float2(u_to_h2(h1.y));

        acc0.x = fmaf(ck, f00.x, acc0.x); acc0.y = fmaf(ck, f00.y, acc0.y);
        acc0.z = fmaf(ck, f01.x, acc0.z); acc0.w = fmaf(ck, f01.y, acc0.w);
        acc1.x = fmaf(ck, f10.x, acc1.x); acc1.y = fmaf(ck, f10.y, acc1.y);
        acc1.z = fmaf(ck, f11.x, acc1.z); acc1.w = fmaf(ck, f11.y, acc1.w);
    }

    stcs_v4(reinterpret_cast<float4*>(out + (size_t)n * C_) + lane,          acc0);
    stcs_v4(reinterpret_cast<float4*>(out + (size_t)(N_IN + n) * C_) + lane, acc1);
}

// ---------------------------------------------------------------------------
// Launch
// Inputs (metadata order): 0=x, 1=omega, 2=delta, 3=cand_mask, 4=parent_idx,
//                          5=cand_idx. Output: float32 [B, N_IN, C].
// ---------------------------------------------------------------------------
extern "C" void kernel_launch(void* const* d_in, const int* in_sizes, int n_in,
                              void* d_out, int out_size)
{
    const float* x      = (const float*)d_in[0];
    const float* omega  = (const float*)d_in[1];
    const float* delta  = (const float*)d_in[2];
    const float* mask   = (const float*)d_in[3];
    const int*   parent = (const int*)  d_in[4];
    const int*   cand   = (const int*)  d_in[5];
    float*       out    = (float*)d_out;

    const int blocks_in  = (N_IN  * 32 + 255) / 256;  // one warp per n
    const int blocks_out = (N_OUT * 32 + 255) / 256;  // one warp per j

    scatter_kernel<<<blocks_in, 256>>>(x, omega, parent);
    convert_kernel<<<blocks_out, 256>>>();
    gather_kernel<<<blocks_in, 256>>>(delta, mask, cand, out);
}